// round 6
// baseline (speedup 1.0000x reference)
#include <cuda_runtime.h>
#include <math.h>

#define Bq 4
#define Nn 500
#define Dd 2048
#define Kk 50
#define H0 28
#define C0c 512
#define NP0 (H0*H0)
#define H1 14
#define C1c 1024
#define NP1 (H1*H1)
#define IMG 224
#define KS 33
#define RAD 16

#define KCH0 10
#define KPW0 5
#define KCH1 25
#define KPW1 2
#define BLK0 ((Bq*NP0*KCH0)/8)   // 3920
#define BLK1 ((Bq*NP1*KCH1)/8)   // 2450

#define DIST_BLKS ((Bq*Nn*32 + 255)/256)   // 250

// ---------------- device scratch ----------------
__device__ float    g_d2[Bq*Nn];
__device__ int      g_idx[Bq*Kk];
__device__ unsigned g_mask[Nn];      // which batches selected bank row n
__device__ unsigned g_min0[Bq*NP0];  // min DISTANCE (sqrt'ed), float bits
__device__ unsigned g_min1[Bq*NP1];
__device__ float    g_C0[IMG*H0];    // composite blur*resize operator (y-major)
__device__ float    g_C1[IMG*H1];
__device__ float    g_C0T[H0*IMG];   // transposed (i-major) for coalesced hpass
__device__ float    g_C1T[H1*IMG];

__device__ __forceinline__ int reflect(int i) {
    if (i < 0) return -i;
    if (i > IMG - 1) return 2*(IMG - 1) - i;
    return i;
}

// ---------------- pairwise distances + operator precompute + mask init ----------------
__global__ void dist_kernel(const float* __restrict__ x2,
                            const float* __restrict__ f2) {
    if (blockIdx.x < DIST_BLKS) {
        // zero g_mask (blocks 0 and 1 cover 500 entries)
        if (blockIdx.x < 2) {
            int z = blockIdx.x * 256 + threadIdx.x;
            if (z < Nn) g_mask[z] = 0u;
        }
        int gw = (blockIdx.x * blockDim.x + threadIdx.x) >> 5;
        int lane = threadIdx.x & 31;
        if (gw >= Bq * Nn) return;
        int b = gw / Nn, n = gw % Nn;
        const float4* q = (const float4*)(x2 + (size_t)b * Dd);
        const float4* f = (const float4*)(f2 + (size_t)n * Dd);
        float ss = 0.f;
        #pragma unroll
        for (int j = 0; j < 16; j++) {
            float4 a = q[lane + j*32];
            float4 c = f[lane + j*32];
            float dx = a.x - c.x, dy = a.y - c.y, dz = a.z - c.z, dw = a.w - c.w;
            ss += dx*dx + dy*dy + dz*dz + dw*dw;
        }
        #pragma unroll
        for (int o = 16; o; o >>= 1) ss += __shfl_xor_sync(0xFFFFFFFFu, ss, o);
        if (lane == 0) g_d2[gw] = ss;
        return;
    }
    // ----- operator precompute: C = Blur(33,reflect101) * BilinearUp(H->224) -----
    int lvl = blockIdx.x - DIST_BLKS;          // 0 or 1
    int H = lvl ? H1 : H0;
    float* Cm  = lvl ? g_C1  : g_C0;
    float* CmT = lvl ? g_C1T : g_C0T;
    int y = threadIdx.x;
    if (y >= IMG) return;
    float w[KS];
    float wsum = 0.f;
    #pragma unroll
    for (int o = 0; o < KS; o++) {
        float xx = (float)o - (float)RAD;
        w[o] = expf(-(xx*xx) / (2.0f * 4.0f * 4.0f));
        wsum += w[o];
    }
    __shared__ float sC[IMG * H0];
    float* row = sC + y * H;
    for (int i = 0; i < H; i++) row[i] = 0.f;
    float scale = (float)H / (float)IMG;
    #pragma unroll
    for (int o = 0; o < KS; o++) {
        int t = reflect(y + o - RAD);
        float fy = ((float)t + 0.5f) * scale - 0.5f;
        float f0 = floorf(fy);
        float wf = fy - f0;
        int i0 = (int)f0;
        int i0c = max(i0, 0), i1c = min(i0 + 1, H - 1);
        float ww = w[o] / wsum;
        row[i0c] += ww * (1.f - wf);
        row[i1c] += ww * wf;
    }
    for (int i = 0; i < H; i++) {
        Cm[y * H + i]   = row[i];
        CmT[i * IMG + y] = row[i];
    }
}

// ---------------- select top-K + score + batch mask + init scratch ----------------
__global__ void select_kernel(float* __restrict__ out_score) {
    int b = blockIdx.x;
    int tid = threadIdx.x;
    __shared__ float sd[Nn];
    __shared__ float ssel[Kk];
    for (int i = tid; i < NP0; i += 256) g_min0[b*NP0 + i] = 0x7F800000u;
    for (int i = tid; i < NP1; i += 256) g_min1[b*NP1 + i] = 0x7F800000u;
    for (int n = tid; n < Nn; n += 256) sd[n] = g_d2[b*Nn + n];
    __syncthreads();
    for (int n = tid; n < Nn; n += 256) {
        float dn = sd[n];
        int r = 0;
        for (int m = 0; m < Nn; m++) {
            float dm = sd[m];
            r += (dm < dn) || (dm == dn && m < n);
        }
        if (r < Kk) {
            g_idx[b*Kk + r] = n;
            ssel[r] = sqrtf(fmaxf(dn, 0.f));
            atomicOr(&g_mask[n], 1u << b);
        }
    }
    __syncthreads();
    if (tid == 0) {
        float s = 0.f;
        for (int i = 0; i < Kk; i++) s += ssel[i];
        out_score[b] = s / (float)Kk;
    }
}

// ---------------- min-distance maps with cross-batch dedup ----------------
// Warp slot (b, pix, chunk). For each of its KPW bank rows n: only the LOWEST
// batch that selected n ("owner") processes it, computing distances for ALL
// batches sharing n (f row read once chip-wide; x rows are L1/L2 hits).
template<int C, int NP, int KCH, int KPW>
__device__ __forceinline__ void minmap_body(const float* __restrict__ x,
                                            const float* __restrict__ f,
                                            unsigned* __restrict__ gmin,
                                            int wid, int lane) {
    int chunk = wid % KCH;
    int pix   = (wid / KCH) % NP;
    int b     = wid / (KCH * NP);

    int nn[KPW];
    unsigned msk[KPW];
    bool own[KPW];
    #pragma unroll
    for (int kk = 0; kk < KPW; kk++) {
        nn[kk] = g_idx[b*Kk + chunk*KPW + kk];
        msk[kk] = g_mask[nn[kk]];
        own[kk] = (msk[kk] & ((1u << b) - 1u)) == 0u;   // no lower batch has it
    }

    float part[KPW][Bq];
    #pragma unroll
    for (int kk = 0; kk < KPW; kk++)
        #pragma unroll
        for (int bb = 0; bb < Bq; bb++) part[kk][bb] = 0.f;

    constexpr int NCH = C / 512;
    #pragma unroll
    for (int cc = 0; cc < NCH; cc++) {
        #pragma unroll
        for (int kk = 0; kk < KPW; kk++) {
            if (!own[kk]) continue;                     // warp-uniform
            const float4* fv = (const float4*)(f + ((size_t)nn[kk]*NP + pix)*C + cc*512);
            float4 v[4];
            #pragma unroll
            for (int r = 0; r < 4; r++) v[r] = fv[lane + r*32];
            #pragma unroll
            for (int bb = 0; bb < Bq; bb++) {
                if (!((msk[kk] >> bb) & 1u)) continue;  // warp-uniform
                const float4* xv = (const float4*)(x + ((size_t)(bb*NP + pix))*C + cc*512);
                #pragma unroll
                for (int r = 0; r < 4; r++) {
                    float4 a = xv[lane + r*32];
                    float dx = v[r].x - a.x, dy = v[r].y - a.y;
                    float dz = v[r].z - a.z, dw = v[r].w - a.w;
                    part[kk][bb] += dx*dx + dy*dy + dz*dz + dw*dw;
                }
            }
        }
    }
    #pragma unroll
    for (int kk = 0; kk < KPW; kk++) {
        if (!own[kk]) continue;
        #pragma unroll
        for (int bb = 0; bb < Bq; bb++) {
            if (!((msk[kk] >> bb) & 1u)) continue;
            float s = part[kk][bb];
            #pragma unroll
            for (int o = 16; o; o >>= 1) s += __shfl_xor_sync(0xFFFFFFFFu, s, o);
            if (lane == 0)
                atomicMin(gmin + bb*NP + pix, __float_as_uint(sqrtf(s)));
        }
    }
}

__global__ void minmap_fused(const float* __restrict__ x0, const float* __restrict__ f0,
                             const float* __restrict__ x1, const float* __restrict__ f1) {
    int lane = threadIdx.x & 31;
    int wIn  = threadIdx.x >> 5;
    if (blockIdx.x < BLK0) {
        int wid = blockIdx.x * 8 + wIn;
        minmap_body<C0c, NP0, KCH0, KPW0>(x0, f0, g_min0, wid, lane);
    } else {
        int wid = (blockIdx.x - BLK0) * 8 + wIn;
        minmap_body<C1c, NP1, KCH1, KPW1>(x1, f1, g_min1, wid, lane);
    }
}

// ---------------- fused tail: resize+avg+blur as two smem contractions ----------------
__global__ void tail_kernel(float* __restrict__ out_mask) {
    int row = blockIdx.x;            // b*IMG + y
    int b = row / IMG;
    int y = row % IMG;
    int x = threadIdx.x;             // 0..223

    __shared__ float sm0[NP0];
    __shared__ float sm1[NP1];
    __shared__ float T0[H0];
    __shared__ float T1[H1];

    const unsigned* m0 = g_min0 + b * NP0;
    const unsigned* m1 = g_min1 + b * NP1;
    #pragma unroll
    for (int i = x; i < NP0; i += IMG) sm0[i] = __uint_as_float(m0[i]);
    if (x < NP1) sm1[x] = __uint_as_float(m1[x]);
    __syncthreads();

    // vertical contraction: T[i] = sum_t C[y,t] * m[t,i]
    if (x < H0) {
        const float* Crow = g_C0 + y * H0;
        float s = 0.f;
        #pragma unroll
        for (int t = 0; t < H0; t++) s += Crow[t] * sm0[t*H0 + x];
        T0[x] = s;
    } else if (x >= 32 && x < 32 + H1) {
        int j = x - 32;
        const float* Crow = g_C1 + y * H1;
        float s = 0.f;
        #pragma unroll
        for (int t = 0; t < H1; t++) s += Crow[t] * sm1[t*H1 + j];
        T1[j] = s;
    }
    __syncthreads();

    // horizontal contraction + average — coalesced via transposed operator
    float s0 = 0.f, s1 = 0.f;
    #pragma unroll
    for (int i = 0; i < H0; i++) s0 += g_C0T[i*IMG + x] * T0[i];
    #pragma unroll
    for (int j = 0; j < H1; j++) s1 += g_C1T[j*IMG + x] * T1[j];
    out_mask[row * IMG + x] = 0.5f * (s0 + s1);
}

// ---------------- launch ----------------
extern "C" void kernel_launch(void* const* d_in, const int* in_sizes, int n_in,
                              void* d_out, int out_size) {
    const float* x0 = (const float*)d_in[0];
    const float* x1 = (const float*)d_in[1];
    const float* x2 = (const float*)d_in[2];
    const float* f0 = (const float*)d_in[3];
    const float* f1 = (const float*)d_in[4];
    const float* f2 = (const float*)d_in[5];
    float* out = (float*)d_out;           // [0..3] = score, [4..] = mask

    dist_kernel<<<DIST_BLKS + 2, 256>>>(x2, f2);
    select_kernel<<<Bq, 256>>>(out);
    minmap_fused<<<BLK0 + BLK1, 256>>>(x0, f0, x1, f1);
    tail_kernel<<<Bq * IMG, IMG>>>(out + 4);
}

// round 8
// speedup vs baseline: 1.1919x; 1.1919x over previous
#include <cuda_runtime.h>
#include <math.h>

#define Bq 4
#define Nn 500
#define Dd 2048
#define Kk 50
#define H0 28
#define C0c 512
#define NP0 (H0*H0)
#define H1 14
#define C1c 1024
#define NP1 (H1*H1)
#define IMG 224
#define KS 33
#define RAD 16

#define NU 200            // padded unique-row work list length (<= Bq*Kk)
#define UPW0 5
#define NCH0 (NU/UPW0)    // 40 chunks -> 784*40 = 31360 warps
#define UPW1 2
#define NCH1 (NU/UPW1)    // 100 chunks -> 196*100 = 19600 warps
#define BLK0 ((NP0*NCH0)/8)   // 3920
#define BLK1 ((NP1*NCH1)/8)   // 2450

#define DIST_BLKS ((Bq*Nn*32 + 255)/256)   // 250

// ---------------- device scratch ----------------
__device__ float    g_d2[Bq*Nn];
__device__ unsigned g_mask[Nn];      // batch bitmask per bank row
__device__ unsigned g_list[256];     // compacted (mask<<16)|n, padded w/ 0
__device__ int      g_done;
__device__ int      g_ucount;
__device__ unsigned g_min0[Bq*NP0];  // min DISTANCE (sqrt'ed), float bits
__device__ unsigned g_min1[Bq*NP1];
__device__ float    g_C0[IMG*H0];    // composite blur*resize operator (y-major)
__device__ float    g_C1[IMG*H1];
__device__ float    g_C0T[H0*IMG];   // transposed for coalesced hpass
__device__ float    g_C1T[H1*IMG];

__device__ __forceinline__ int reflect(int i) {
    if (i < 0) return -i;
    if (i > IMG - 1) return 2*(IMG - 1) - i;
    return i;
}

// ---------------- pairwise distances + operator precompute + scratch init ----------------
__global__ void dist_kernel(const float* __restrict__ x2,
                            const float* __restrict__ f2) {
    if (blockIdx.x < DIST_BLKS) {
        if (blockIdx.x < 2) {                      // zero g_mask
            int z = blockIdx.x * 256 + threadIdx.x;
            if (z < Nn) g_mask[z] = 0u;
        } else if (blockIdx.x == 2) {              // zero list + counters
            if (threadIdx.x < 256) g_list[threadIdx.x] = 0u;
            if (threadIdx.x == 0) { g_done = 0; g_ucount = 0; }
        }
        int gw = (blockIdx.x * blockDim.x + threadIdx.x) >> 5;
        int lane = threadIdx.x & 31;
        if (gw >= Bq * Nn) return;
        int b = gw / Nn, n = gw % Nn;
        const float4* q = (const float4*)(x2 + (size_t)b * Dd);
        const float4* f = (const float4*)(f2 + (size_t)n * Dd);
        float ss = 0.f;
        #pragma unroll
        for (int j = 0; j < 16; j++) {
            float4 a = q[lane + j*32];
            float4 c = f[lane + j*32];
            float dx = a.x - c.x, dy = a.y - c.y, dz = a.z - c.z, dw = a.w - c.w;
            ss += dx*dx + dy*dy + dz*dz + dw*dw;
        }
        #pragma unroll
        for (int o = 16; o; o >>= 1) ss += __shfl_xor_sync(0xFFFFFFFFu, ss, o);
        if (lane == 0) g_d2[gw] = ss;
        return;
    }
    // ----- operator precompute: C = Blur(33,reflect101) * BilinearUp(H->224) -----
    int lvl = blockIdx.x - DIST_BLKS;          // 0 or 1
    int H = lvl ? H1 : H0;
    float* Cm  = lvl ? g_C1  : g_C0;
    float* CmT = lvl ? g_C1T : g_C0T;
    int y = threadIdx.x;
    if (y >= IMG) return;
    float w[KS];
    float wsum = 0.f;
    #pragma unroll
    for (int o = 0; o < KS; o++) {
        float xx = (float)o - (float)RAD;
        w[o] = expf(-(xx*xx) / (2.0f * 4.0f * 4.0f));
        wsum += w[o];
    }
    __shared__ float sC[IMG * H0];
    float* row = sC + y * H;
    for (int i = 0; i < H; i++) row[i] = 0.f;
    float scale = (float)H / (float)IMG;
    #pragma unroll
    for (int o = 0; o < KS; o++) {
        int t = reflect(y + o - RAD);
        float fy = ((float)t + 0.5f) * scale - 0.5f;
        float f0 = floorf(fy);
        float wf = fy - f0;
        int i0 = (int)f0;
        int i0c = max(i0, 0), i1c = min(i0 + 1, H - 1);
        float ww = w[o] / wsum;
        row[i0c] += ww * (1.f - wf);
        row[i1c] += ww * wf;
    }
    for (int i = 0; i < H; i++) {
        Cm[y * H + i]    = row[i];
        CmT[i * IMG + y] = row[i];
    }
}

// ---------------- select top-K + score + mask; LAST block compacts work list ----------------
__global__ void select_kernel(float* __restrict__ out_score) {
    int b = blockIdx.x;
    int tid = threadIdx.x;
    __shared__ float sd[Nn];
    __shared__ float ssel[Kk];
    __shared__ int sdone;
    for (int i = tid; i < NP0; i += 256) g_min0[b*NP0 + i] = 0x7F800000u;
    for (int i = tid; i < NP1; i += 256) g_min1[b*NP1 + i] = 0x7F800000u;
    for (int n = tid; n < Nn; n += 256) sd[n] = g_d2[b*Nn + n];
    __syncthreads();
    for (int n = tid; n < Nn; n += 256) {
        float dn = sd[n];
        int r = 0;
        for (int m = 0; m < Nn; m++) {
            float dm = sd[m];
            r += (dm < dn) || (dm == dn && m < n);
        }
        if (r < Kk) {
            ssel[r] = sqrtf(fmaxf(dn, 0.f));
            atomicOr(&g_mask[n], 1u << b);
        }
    }
    __syncthreads();
    if (tid == 0) {
        float s = 0.f;
        for (int i = 0; i < Kk; i++) s += ssel[i];
        out_score[b] = s / (float)Kk;
    }
    // publish mask writes, then last-arriving block builds the work list
    __threadfence();
    if (tid == 0) sdone = atomicAdd(&g_done, 1);
    __syncthreads();
    if (sdone == Bq - 1) {
        __threadfence();
        for (int n = tid; n < Nn; n += 256) {
            unsigned m = atomicOr(&g_mask[n], 0u);   // atomic read
            if (m) {
                int p = atomicAdd(&g_ucount, 1);
                g_list[p] = (m << 16) | (unsigned)n;
            }
        }
    }
}

// ---------------- min-distance maps: balanced unique-row work list ----------------
// warp = (pixel, chunk of UPW units). Every warp loads UPW DRAM f-rows (balanced);
// x-rows are L2-hot. Each f byte read once chip-wide.
template<int C, int NP, int UPW, int NCH>
__device__ __forceinline__ void minmap_body(const float* __restrict__ x,
                                            const float* __restrict__ f,
                                            unsigned* __restrict__ gmin,
                                            int wid, int lane) {
    int chunk = wid % NCH;
    int pix   = wid / NCH;

    float mn[Bq];
    #pragma unroll
    for (int bb = 0; bb < Bq; bb++) mn[bb] = 3.4e38f;
    unsigned seen = 0u;

    #pragma unroll
    for (int uu = 0; uu < UPW; uu++) {
        unsigned e = g_list[chunk*UPW + uu];
        unsigned msk = e >> 16;
        if (!msk) continue;                        // warp-uniform
        int n = e & 0xFFFFu;
        seen |= msk;

        float acc[Bq];
        #pragma unroll
        for (int bb = 0; bb < Bq; bb++) acc[bb] = 0.f;

        constexpr int NCC = C / 512;
        #pragma unroll
        for (int cc = 0; cc < NCC; cc++) {
            const float4* fv = (const float4*)(f + ((size_t)n*NP + pix)*C + cc*512);
            float4 v[4];
            #pragma unroll
            for (int r = 0; r < 4; r++) v[r] = fv[lane + r*32];
            #pragma unroll
            for (int bb = 0; bb < Bq; bb++) {
                if (!((msk >> bb) & 1u)) continue; // warp-uniform
                const float4* xv = (const float4*)(x + ((size_t)(bb*NP + pix))*C + cc*512);
                #pragma unroll
                for (int r = 0; r < 4; r++) {
                    float4 a = xv[lane + r*32];
                    float dx = v[r].x - a.x, dy = v[r].y - a.y;
                    float dz = v[r].z - a.z, dw = v[r].w - a.w;
                    acc[bb] += dx*dx + dy*dy + dz*dz + dw*dw;
                }
            }
        }
        #pragma unroll
        for (int bb = 0; bb < Bq; bb++) {
            if (!((msk >> bb) & 1u)) continue;
            float s = acc[bb];
            #pragma unroll
            for (int o = 16; o; o >>= 1) s += __shfl_xor_sync(0xFFFFFFFFu, s, o);
            mn[bb] = fminf(mn[bb], s);
        }
    }
    if (lane == 0) {
        #pragma unroll
        for (int bb = 0; bb < Bq; bb++)
            if ((seen >> bb) & 1u)
                atomicMin(gmin + bb*NP + pix, __float_as_uint(sqrtf(mn[bb])));
    }
}

__global__ void minmap_fused(const float* __restrict__ x0, const float* __restrict__ f0,
                             const float* __restrict__ x1, const float* __restrict__ f1) {
    int lane = threadIdx.x & 31;
    int wIn  = threadIdx.x >> 5;
    if (blockIdx.x < BLK0) {
        int wid = blockIdx.x * 8 + wIn;
        minmap_body<C0c, NP0, UPW0, NCH0>(x0, f0, g_min0, wid, lane);
    } else {
        int wid = (blockIdx.x - BLK0) * 8 + wIn;
        minmap_body<C1c, NP1, UPW1, NCH1>(x1, f1, g_min1, wid, lane);
    }
}

// ---------------- fused tail: direct-read vpass + coalesced hpass ----------------
__global__ void tail_kernel(float* __restrict__ out_mask) {
    int row = blockIdx.x;            // b*IMG + y
    int b = row / IMG;
    int y = row % IMG;
    int x = threadIdx.x;             // 0..223

    __shared__ float T0[H0];
    __shared__ float T1[H1];

    // vertical contraction: T[i] = sum_t C[y,t] * m[t,i]  (each m read once -> no staging)
    if (x < H0) {
        const float* Crow = g_C0 + y * H0;
        const unsigned* m0 = g_min0 + b * NP0;
        float s = 0.f;
        #pragma unroll
        for (int t = 0; t < H0; t++) s += Crow[t] * __uint_as_float(m0[t*H0 + x]);
        T0[x] = s;
    } else if (x >= 32 && x < 32 + H1) {
        int j = x - 32;
        const float* Crow = g_C1 + y * H1;
        const unsigned* m1 = g_min1 + b * NP1;
        float s = 0.f;
        #pragma unroll
        for (int t = 0; t < H1; t++) s += Crow[t] * __uint_as_float(m1[t*H1 + j]);
        T1[j] = s;
    }
    __syncthreads();

    // horizontal contraction + average — coalesced via transposed operator
    float s0 = 0.f, s1 = 0.f;
    #pragma unroll
    for (int i = 0; i < H0; i++) s0 += g_C0T[i*IMG + x] * T0[i];
    #pragma unroll
    for (int j = 0; j < H1; j++) s1 += g_C1T[j*IMG + x] * T1[j];
    out_mask[row * IMG + x] = 0.5f * (s0 + s1);
}

// ---------------- launch ----------------
extern "C" void kernel_launch(void* const* d_in, const int* in_sizes, int n_in,
                              void* d_out, int out_size) {
    const float* x0 = (const float*)d_in[0];
    const float* x1 = (const float*)d_in[1];
    const float* x2 = (const float*)d_in[2];
    const float* f0 = (const float*)d_in[3];
    const float* f1 = (const float*)d_in[4];
    const float* f2 = (const float*)d_in[5];
    float* out = (float*)d_out;           // [0..3] = score, [4..] = mask

    dist_kernel<<<DIST_BLKS + 2, 256>>>(x2, f2);
    select_kernel<<<Bq, 256>>>(out);
    minmap_fused<<<BLK0 + BLK1, 256>>>(x0, f0, x1, f1);
    tail_kernel<<<Bq * IMG, IMG>>>(out + 4);
}